// round 2
// baseline (speedup 1.0000x reference)
#include <cuda_runtime.h>

#define T_STEPS 2048
#define N_RES   2048
#define D_IN    128
#define NCTA    128
#define NTHR    512
#define ROWS_PER_CTA 16
#define INV_SQRT_N 0.022097086912079608f  // 1/sqrt(2048)

// Scratch: precomputed input projections U[t][n] (16 MB) + barrier counter.
__device__ float        g_U[(size_t)T_STEPS * N_RES];
__device__ unsigned int g_counter;

__global__ void esn_init() { g_counter = 0u; }

__global__ void __launch_bounds__(NTHR, 1) esn_main(
    const float* __restrict__ input,   // [T, D]
    const float* __restrict__ W_in,    // [N, D]
    const float* __restrict__ W_res,   // [N, N]
    float* __restrict__ out)           // [T, N]  (row t == x_t)
{
    const int tid   = threadIdx.x;
    const int b     = blockIdx.x;
    const int rbase = b * ROWS_PER_CTA;
    const int l     = tid & 31;
    const int w     = tid >> 5;          // warp 0..15
    const int rowg  = w & 3;             // 4 row-groups of 4 rows
    const int colg  = w >> 2;            // 4 col-groups of 512 cols
    const int cbase = colg * 512;

    __shared__ float sh[2048];           // W_in slice (phase U), then x_prev (phase R)
    __shared__ float part[16][4];

    // ================= Phase U: U = input @ W_in^T (own 16 columns) ============
    // W_in rows [rbase, rbase+16) are contiguous: 2048 floats -> shared.
    ((float4*)sh)[tid] = ((const float4*)(W_in + (size_t)rbase * D_IN))[tid];
    __syncthreads();

    for (int k = 0; k < 4; ++k) {
        const int t = tid + NTHR * k;
        float acc[16];
        #pragma unroll
        for (int n = 0; n < 16; ++n) acc[n] = 0.f;
        const float4* inrow = (const float4*)(input + (size_t)t * D_IN);
        for (int jd = 0; jd < 32; ++jd) {
            float4 iv = __ldg(inrow + jd);
            #pragma unroll
            for (int n = 0; n < 16; ++n) {
                float4 wv = ((const float4*)sh)[n * 32 + jd];   // broadcast LDS
                acc[n] = fmaf(iv.x, wv.x, acc[n]);
                acc[n] = fmaf(iv.y, wv.y, acc[n]);
                acc[n] = fmaf(iv.z, wv.z, acc[n]);
                acc[n] = fmaf(iv.w, wv.w, acc[n]);
            }
        }
        float4* urow = (float4*)(g_U + (size_t)t * N_RES + rbase);
        #pragma unroll
        for (int q = 0; q < 4; ++q)
            urow[q] = make_float4(acc[4*q], acc[4*q+1], acc[4*q+2], acc[4*q+3]);
    }
    __syncthreads();   // before reusing sh[] as x buffer

    // ============ Load recurrence weights into registers (64 floats/thread) ====
    // Thread covers rows rbase+rowg*4+i (i<4), column pairs cbase+2l+64j (+0/1, j<8).
    unsigned long long wreg[4][8];
    #pragma unroll
    for (int i = 0; i < 4; ++i) {
        const float* wrow = W_res + (size_t)(rbase + rowg * 4 + i) * N_RES + cbase + 2 * l;
        #pragma unroll
        for (int j = 0; j < 8; ++j)
            wreg[i][j] = *(const unsigned long long*)(wrow + 64 * j);
    }

    // ================= t = 0: x0 = erf(U[0]) / sqrt(N) =========================
    if (tid < 16) {
        float u = g_U[rbase + tid];
        out[rbase + tid] = erff(u) * INV_SQRT_N;
        __threadfence();
    }
    __syncthreads();
    if (tid == 0)
        asm volatile("red.release.gpu.global.add.u32 [%0], %1;"
                     :: "l"(&g_counter), "r"(1u) : "memory");

    // ================= Recurrence ==============================================
    for (int t = 1; t < T_STEPS; ++t) {
        // Prefetch own U row (ready — no cross-CTA dep) while waiting on barrier.
        float u = 0.f;
        if (tid < 16) u = g_U[(size_t)t * N_RES + rbase + tid];

        if (tid == 0) {
            const unsigned target = (unsigned)NCTA * (unsigned)t;
            unsigned v;
            do {
                asm volatile("ld.acquire.gpu.global.u32 %0, [%1];"
                             : "=r"(v) : "l"(&g_counter));
            } while (v < target);
        }
        __syncthreads();

        // Stage x_prev = out[t-1] into shared (bypass L1: written by other SMs).
        {
            const float4* src = (const float4*)(out + (size_t)(t - 1) * N_RES);
            ((float4*)sh)[tid] = __ldcg(src + tid);
        }
        __syncthreads();

        // Dot products: 4 rows x 16 cols per thread via packed f32x2 FMA.
        unsigned long long xr[8];
        const float* xp = sh + cbase + 2 * l;
        #pragma unroll
        for (int j = 0; j < 8; ++j)
            xr[j] = *(const unsigned long long*)(xp + 64 * j);

        unsigned long long acc[4] = {0ull, 0ull, 0ull, 0ull};
        #pragma unroll
        for (int j = 0; j < 8; ++j) {
            #pragma unroll
            for (int i = 0; i < 4; ++i)
                asm volatile("fma.rn.f32x2 %0, %1, %2, %0;"
                             : "+l"(acc[i]) : "l"(wreg[i][j]), "l"(xr[j]));
        }

        float s[4];
        #pragma unroll
        for (int i = 0; i < 4; ++i) {
            float2 f = *reinterpret_cast<float2*>(&acc[i]);
            s[i] = f.x + f.y;
        }
        #pragma unroll
        for (int off = 16; off > 0; off >>= 1) {
            #pragma unroll
            for (int i = 0; i < 4; ++i)
                s[i] += __shfl_xor_sync(0xFFFFFFFFu, s[i], off);
        }
        if (l == 0) {
            #pragma unroll
            for (int i = 0; i < 4; ++i)
                part[rowg * 4 + i][colg] = s[i];
        }
        __syncthreads();

        if (tid < 16) {
            float pre = part[tid][0] + part[tid][1] + part[tid][2] + part[tid][3] + u;
            out[(size_t)t * N_RES + rbase + tid] = erff(pre) * INV_SQRT_N;
            __threadfence();
        }
        __syncthreads();
        if (tid == 0)
            asm volatile("red.release.gpu.global.add.u32 [%0], %1;"
                         :: "l"(&g_counter), "r"(1u) : "memory");
    }
}

extern "C" void kernel_launch(void* const* d_in, const int* in_sizes, int n_in,
                              void* d_out, int out_size)
{
    const float* input = (const float*)d_in[0];   // (2048, 128)
    const float* W_in  = (const float*)d_in[1];   // (2048, 128)
    const float* W_res = (const float*)d_in[2];   // (2048, 2048)
    float* out = (float*)d_out;                   // (2048, 2048)

    esn_init<<<1, 1>>>();
    esn_main<<<NCTA, NTHR>>>(input, W_in, W_res, out);
}

// round 3
// speedup vs baseline: 1.1062x; 1.1062x over previous
#include <cuda_runtime.h>

#define T_STEPS 2048
#define N_RES   2048
#define D_IN    128
#define NCTA    128
#define NTHR    512
#define ROWS_PER_CTA 16
#define NBANK   8
#define INV_SQRT_N 0.022097086912079608f  // 1/sqrt(2048)

// Scratch: precomputed input projections U[t][n] (16 MB) + banked barrier counters.
__device__ float        g_U[(size_t)T_STEPS * N_RES];
__device__ unsigned int g_counter[NBANK * 32];   // one counter per 128B line

__global__ void esn_init() {
    if (threadIdx.x < NBANK * 32) g_counter[threadIdx.x] = 0u;
}

__global__ void __launch_bounds__(NTHR, 1) esn_main(
    const float* __restrict__ input,   // [T, D]
    const float* __restrict__ W_in,    // [N, D]
    const float* __restrict__ W_res,   // [N, N]
    float* __restrict__ out)           // [T, N]  (row t == x_t)
{
    const int tid   = threadIdx.x;
    const int b     = blockIdx.x;
    const int rbase = b * ROWS_PER_CTA;
    const int l     = tid & 31;
    const int w     = tid >> 5;          // warp 0..15
    const int rowg  = w & 3;             // 4 row-groups of 4 rows
    const int colg  = w >> 2;            // 4 col-groups of 512 cols
    const int cbase = colg * 512;

    __shared__ float sh[2048];           // W_in slice (phase U only)
    __shared__ float part[4][16];        // [colg][row]
    __shared__ unsigned int sh_flag;     // epoch published by warp 0

    unsigned int* mybank = g_counter + (b & (NBANK - 1)) * 32;

    // ================= Phase U: U = input @ W_in^T (own 16 columns) ============
    ((float4*)sh)[tid] = ((const float4*)(W_in + (size_t)rbase * D_IN))[tid];
    if (tid == 0) sh_flag = 0u;
    __syncthreads();

    for (int k = 0; k < 4; ++k) {
        const int t = tid + NTHR * k;
        float acc[16];
        #pragma unroll
        for (int n = 0; n < 16; ++n) acc[n] = 0.f;
        const float4* inrow = (const float4*)(input + (size_t)t * D_IN);
        for (int jd = 0; jd < 32; ++jd) {
            float4 iv = __ldg(inrow + jd);
            #pragma unroll
            for (int n = 0; n < 16; ++n) {
                float4 wv = ((const float4*)sh)[n * 32 + jd];
                acc[n] = fmaf(iv.x, wv.x, acc[n]);
                acc[n] = fmaf(iv.y, wv.y, acc[n]);
                acc[n] = fmaf(iv.z, wv.z, acc[n]);
                acc[n] = fmaf(iv.w, wv.w, acc[n]);
            }
        }
        float4* urow = (float4*)(g_U + (size_t)t * N_RES + rbase);
        #pragma unroll
        for (int q = 0; q < 4; ++q)
            urow[q] = make_float4(acc[4*q], acc[4*q+1], acc[4*q+2], acc[4*q+3]);
    }
    __syncthreads();

    // ============ Load recurrence weights into registers (64 floats/thread) ====
    unsigned long long wreg[4][8];
    #pragma unroll
    for (int i = 0; i < 4; ++i) {
        const float* wrow = W_res + (size_t)(rbase + rowg * 4 + i) * N_RES + cbase + 2 * l;
        #pragma unroll
        for (int j = 0; j < 8; ++j)
            wreg[i][j] = *(const unsigned long long*)(wrow + 64 * j);
    }

    // ================= t = 0: x0 = erf(U[0]) / sqrt(N) =========================
    if (w == 0) {
        if (l < 16) {
            float u0 = g_U[rbase + l];
            out[rbase + l] = erff(u0) * INV_SQRT_N;
        }
        __syncwarp();
        if (l == 0)
            asm volatile("red.release.gpu.global.add.u32 [%0], %1;"
                         :: "l"(mybank), "r"(1u) : "memory");
    }

    // ================= Recurrence ==============================================
    for (int t = 1; t < T_STEPS; ++t) {
        float u = 0.f;
        if (w == 0) {
            if (l < 16) u = g_U[(size_t)t * N_RES + rbase + l];   // prefetch own U
            if (l < 8) {
                const unsigned target = 16u * (unsigned)t;
                unsigned int* bank = g_counter + l * 32;
                unsigned v;
                do {
                    asm volatile("ld.acquire.gpu.global.u32 %0, [%1];"
                                 : "=r"(v) : "l"(bank) : "memory");
                } while (v < target);
            }
            __syncwarp();
            if (l == 0)
                asm volatile("st.release.cta.u32 [%0], %1;"
                             :: "l"(&sh_flag), "r"((unsigned)t) : "memory");
        } else {
            unsigned e;
            do {
                asm volatile("ld.acquire.cta.u32 %0, [%1];"
                             : "=r"(e) : "l"(&sh_flag) : "memory");
            } while (e < (unsigned)t);
        }

        // Load x_prev straight from global (L1-cacheable: fresh lines every step;
        // the 4 warps sharing a column group hit L1 after the first miss).
        const float* xp = out + (size_t)(t - 1) * N_RES + cbase + 2 * l;
        unsigned long long xr[8];
        #pragma unroll
        for (int j = 0; j < 8; ++j)
            xr[j] = *(const unsigned long long*)(xp + 64 * j);

        // Dot products: 4 rows x 16 cols per thread via packed f32x2 FMA.
        unsigned long long acc[4] = {0ull, 0ull, 0ull, 0ull};
        #pragma unroll
        for (int j = 0; j < 8; ++j) {
            #pragma unroll
            for (int i = 0; i < 4; ++i)
                asm volatile("fma.rn.f32x2 %0, %1, %2, %0;"
                             : "+l"(acc[i]) : "l"(wreg[i][j]), "l"(xr[j]));
        }

        float s[4];
        #pragma unroll
        for (int i = 0; i < 4; ++i) {
            float2 f = *reinterpret_cast<float2*>(&acc[i]);
            s[i] = f.x + f.y;
        }
        #pragma unroll
        for (int off = 16; off > 0; off >>= 1) {
            #pragma unroll
            for (int i = 0; i < 4; ++i)
                s[i] += __shfl_xor_sync(0xFFFFFFFFu, s[i], off);
        }
        if (l == 0) {
            #pragma unroll
            for (int i = 0; i < 4; ++i)
                part[colg][rowg * 4 + i] = s[i];
        }
        __syncthreads();

        if (w == 0) {
            if (l < 16) {
                float pre = part[0][l] + part[1][l] + part[2][l] + part[3][l] + u;
                out[(size_t)t * N_RES + rbase + l] = erff(pre) * INV_SQRT_N;
            }
            __syncwarp();
            if (l == 0)
                asm volatile("red.release.gpu.global.add.u32 [%0], %1;"
                             :: "l"(mybank), "r"(1u) : "memory");
        }
    }
}

extern "C" void kernel_launch(void* const* d_in, const int* in_sizes, int n_in,
                              void* d_out, int out_size)
{
    const float* input = (const float*)d_in[0];   // (2048, 128)
    const float* W_in  = (const float*)d_in[1];   // (2048, 128)
    const float* W_res = (const float*)d_in[2];   // (2048, 2048)
    float* out = (float*)d_out;                   // (2048, 2048)

    esn_init<<<1, 256>>>();
    esn_main<<<NCTA, NTHR>>>(input, W_in, W_res, out);
}

// round 4
// speedup vs baseline: 1.4534x; 1.3139x over previous
#include <cuda_runtime.h>

#define T_STEPS 2048
#define N_RES   2048
#define D_IN    128
#define NCTA    128
#define NTHR    512
#define ROWS_PER_CTA 16
#define INV_SQRT_N 0.022097086912079608f  // 1/sqrt(2048)

// Scratch: precomputed input projections U[t][n] (16 MB).
__device__ float g_U[(size_t)T_STEPS * N_RES];

// Prefill out with qNaN sentinel: real x values are erf(..)/sqrt(N), never NaN.
__global__ void esn_prefill(float4* __restrict__ out4) {
    const float qn = __uint_as_float(0x7FC00000u);
    const float4 nv = make_float4(qn, qn, qn, qn);
    const size_t total = (size_t)T_STEPS * N_RES / 4;
    const size_t stride = (size_t)gridDim.x * blockDim.x;
    for (size_t i = (size_t)blockIdx.x * blockDim.x + threadIdx.x; i < total; i += stride)
        out4[i] = nv;
}

__global__ void __launch_bounds__(NTHR, 1) esn_main(
    const float* __restrict__ input,   // [T, D]
    const float* __restrict__ W_in,    // [N, D]
    const float* __restrict__ W_res,   // [N, N]
    float* __restrict__ out)           // [T, N]  (row t == x_t)
{
    const int tid   = threadIdx.x;
    const int b     = blockIdx.x;
    const int rbase = b * ROWS_PER_CTA;
    const int l     = tid & 31;
    const int w     = tid >> 5;          // warp 0..15
    const int rowg  = w & 3;             // 4 row-groups of 4 rows
    const int colg  = w >> 2;            // 4 col-groups of 512 cols
    const int cbase = colg * 512;

    __shared__ float sh[2048];           // W_in slice (phase U only)
    __shared__ float part[2][4][16];     // ping-pong: [t&1][colg][row]

    // ================= Phase U: U = input @ W_in^T (own 16 columns) ============
    ((float4*)sh)[tid] = ((const float4*)(W_in + (size_t)rbase * D_IN))[tid];
    __syncthreads();

    for (int k = 0; k < 4; ++k) {
        const int t = tid + NTHR * k;
        float acc[16];
        #pragma unroll
        for (int n = 0; n < 16; ++n) acc[n] = 0.f;
        const float4* inrow = (const float4*)(input + (size_t)t * D_IN);
        for (int jd = 0; jd < 32; ++jd) {
            float4 iv = __ldg(inrow + jd);
            #pragma unroll
            for (int n = 0; n < 16; ++n) {
                float4 wv = ((const float4*)sh)[n * 32 + jd];
                acc[n] = fmaf(iv.x, wv.x, acc[n]);
                acc[n] = fmaf(iv.y, wv.y, acc[n]);
                acc[n] = fmaf(iv.z, wv.z, acc[n]);
                acc[n] = fmaf(iv.w, wv.w, acc[n]);
            }
        }
        float4* urow = (float4*)(g_U + (size_t)t * N_RES + rbase);
        #pragma unroll
        for (int q = 0; q < 4; ++q)
            urow[q] = make_float4(acc[4*q], acc[4*q+1], acc[4*q+2], acc[4*q+3]);
    }
    __syncthreads();

    // ============ Load recurrence weights into registers (64 floats/thread) ====
    unsigned long long wreg[4][8];
    #pragma unroll
    for (int i = 0; i < 4; ++i) {
        const float* wrow = W_res + (size_t)(rbase + rowg * 4 + i) * N_RES + cbase + 2 * l;
        #pragma unroll
        for (int j = 0; j < 8; ++j)
            wreg[i][j] = *(const unsigned long long*)(wrow + 64 * j);
    }

    // ================= t = 0: x0 = erf(U[0]) / sqrt(N) =========================
    if (w == 0 && l < 16) {
        float u0 = g_U[rbase + l];
        __stcg(&out[rbase + l], erff(u0) * INV_SQRT_N);
    }

    // ================= Recurrence (data-as-flag, NaN sentinel) =================
    for (int t = 1; t < T_STEPS; ++t) {
        const int p = t & 1;
        float u = 0.f;
        if (w == 0 && l < 16) u = g_U[(size_t)t * N_RES + rbase + l];

        const float* xp = out + (size_t)(t - 1) * N_RES + cbase + 2 * l;

        // Speculative load (plain LDG: lines are fresh; 4 warps/colgroup share L1).
        unsigned long long xr[8];
        #pragma unroll
        for (int j = 0; j < 8; ++j)
            xr[j] = *(const unsigned long long*)(xp + 64 * j);

        unsigned long long acc[4];
        float s[4];
        bool nan;

        // Dot + aggregate NaN check (NaN sentinel propagates through FMA).
        #define ESN_DOT()                                                        \
        do {                                                                     \
            acc[0] = acc[1] = acc[2] = acc[3] = 0ull;                            \
            _Pragma("unroll")                                                    \
            for (int j = 0; j < 8; ++j) {                                        \
                _Pragma("unroll")                                                \
                for (int i = 0; i < 4; ++i)                                      \
                    asm volatile("fma.rn.f32x2 %0, %1, %2, %0;"                  \
                                 : "+l"(acc[i]) : "l"(wreg[i][j]), "l"(xr[j]));  \
            }                                                                    \
            _Pragma("unroll")                                                    \
            for (int i = 0; i < 4; ++i) {                                        \
                float2 f = *reinterpret_cast<float2*>(&acc[i]);                  \
                s[i] = f.x + f.y;                                                \
            }                                                                    \
            nan = (s[0] != s[0]) | (s[1] != s[1]) |                              \
                  (s[2] != s[2]) | (s[3] != s[3]);                               \
        } while (0)

        ESN_DOT();

        while (__any_sync(0xFFFFFFFFu, nan)) {
            // Reload only the words that are still sentinel, bypassing L1.
            #pragma unroll
            for (int j = 0; j < 8; ++j) {
                float2 f = *reinterpret_cast<float2*>(&xr[j]);
                if ((f.x != f.x) | (f.y != f.y))
                    asm volatile("ld.global.cg.b64 %0, [%1];"
                                 : "=l"(xr[j]) : "l"(xp + 64 * j) : "memory");
            }
            ESN_DOT();
        }
        #undef ESN_DOT

        // Warp reduce: 4 row-partials per warp.
        #pragma unroll
        for (int off = 16; off > 0; off >>= 1) {
            #pragma unroll
            for (int i = 0; i < 4; ++i)
                s[i] += __shfl_xor_sync(0xFFFFFFFFu, s[i], off);
        }
        if (l == 0) {
            #pragma unroll
            for (int i = 0; i < 4; ++i)
                part[p][colg][rowg * 4 + i] = s[i];
        }
        __syncthreads();   // the only barrier per step (part[] is ping-ponged)

        if (w == 0 && l < 16) {
            float pre = part[p][0][l] + part[p][1][l] + part[p][2][l]
                      + part[p][3][l] + u;
            __stcg(&out[(size_t)t * N_RES + rbase + l], erff(pre) * INV_SQRT_N);
        }
    }
}

extern "C" void kernel_launch(void* const* d_in, const int* in_sizes, int n_in,
                              void* d_out, int out_size)
{
    const float* input = (const float*)d_in[0];   // (2048, 128)
    const float* W_in  = (const float*)d_in[1];   // (2048, 128)
    const float* W_res = (const float*)d_in[2];   // (2048, 2048)
    float* out = (float*)d_out;                   // (2048, 2048)

    esn_prefill<<<NCTA, NTHR>>>((float4*)out);
    esn_main<<<NCTA, NTHR>>>(input, W_in, W_res, out);
}